// round 10
// baseline (speedup 1.0000x reference)
#include <cuda_runtime.h>
#include <math.h>

#define T_LEN   2000000
#define NTAGS   5
#define START_T 3
#define STOP_T  4
#define LN2_D   0.6931471805599453

// stage0 granularity: 4 steps per G-lane
#define NGRP    500000
#define NBLK0   1954                    // ceil(NGRP/256)
#define PAD0    (NBLK0 * 256)           // 500224

// emulate granularity: 8 steps per lane
#define CHUNK   8
#define LANES_ACT 250000
#define L_LAST    (LANES_ACT - 1)
#define NBLK1     977                   // ceil(LANES_ACT/256)

#define K2_ITEMS  8                     // 256*8 = 2048 >= NBLK0

// F_c[i] = feats[(i+1)*5 + c]  (i = global step index - 1)
__device__ float g_F0[4 * PAD0];
__device__ float g_F1[4 * PAD0];
__device__ float g_F2[4 * PAD0];

__device__ float  g_Pinc[9 * PAD0];   // stage0-block-local inclusive prefix (SoA)
__device__ int    g_pb[PAD0];
__device__ float  g_goldB[NBLK0];
__device__ float  g_Mblk[NBLK0][9];   // per-stage0-block totals
__device__ int    g_Bblk[NBLK0];
__device__ float  g_Ebf[NBLK0][9];    // per-stage0-block exclusive prefix
__device__ int    g_EbB[NBLK0];
__device__ float  g_u0f[3];
__device__ float  g_v0f[3];
__device__ double g_c0d;
__device__ double g_partB[NBLK1];
__device__ float  g_stop3[3];
__device__ unsigned g_tick1, g_tick2;

__device__ __forceinline__ void renorm9(float* P, int& base) {
    float m = fmaxf(fmaxf(fmaxf(P[0], P[1]), fmaxf(P[2], P[3])),
                    fmaxf(fmaxf(P[4], P[5]), fmaxf(P[6], fmaxf(P[7], P[8]))));
    int e = (int)(__float_as_uint(m) >> 23) - 127;
    float sc = __uint_as_float((unsigned)(127 - e) << 23);
#pragma unroll
    for (int i = 0; i < 9; ++i) P[i] *= sc;
    base += e;
}

__device__ __forceinline__ void mm9(const float* Bm, const float* A, float* C) {
#pragma unroll
    for (int i = 0; i < 3; ++i)
#pragma unroll
        for (int j = 0; j < 3; ++j)
            C[i*3+j] = Bm[i*3+0]*A[0+j] + Bm[i*3+1]*A[3+j] + Bm[i*3+2]*A[6+j];
}

// ========== K1: fused stage (coalesced load + F write + gold + matrices + scans) ==
__global__ void __launch_bounds__(256) k_stage(
        const float* __restrict__ feats, const int* __restrict__ tags,
        const float* __restrict__ trans) {
    __shared__ float sTr[25];
    __shared__ float sRed[256];
    __shared__ float sT9[8][9];  __shared__ int sbT[8];
    __shared__ float sWE[8][9];  __shared__ int sbWE[8];
    __shared__ float sP[256][9]; __shared__ int sB[256];
    __shared__ bool  sLast;

    const float L2E = 1.4426950408889634f;
    int tid = threadIdx.x, lane = tid & 31, wid = tid >> 5;
    if (tid < 25) sTr[tid] = trans[tid];

    float Tl[9];
#pragma unroll
    for (int i = 0; i < 3; ++i)
#pragma unroll
        for (int k = 0; k < 3; ++k)
            Tl[i*3+k] = exp2f(L2E * __ldg(&trans[i * NTAGS + k]));
    __syncthreads();

    int G = blockIdx.x * 256 + tid;
    float gold = 0.f;
    float f0s[4], f1s[4], f2s[4];
    int n4 = 0;

    if (G < NGRP) {
        const float4* fp = (const float4*)feats;
        int q = 5 * G + 1;
        float4 v0, v1, v2, v3, v4;
        if (G < NGRP - 1) {
            v0 = fp[q];     v1 = fp[q + 1]; v2 = fp[q + 2];
            v3 = fp[q + 3]; v4 = fp[q + 4];
        } else {
            v0 = fp[q];     v1 = fp[q + 1]; v2 = fp[q + 2]; v3 = fp[q + 3];
            v4 = make_float4(0.f, 0.f, 0.f, 0.f);
        }
        float4 w0 = make_float4(v0.y, v1.z, v2.w, v4.x);
        float4 w1 = make_float4(v0.z, v1.w, v3.x, v4.y);
        float4 w2 = make_float4(v0.w, v2.x, v3.y, v4.z);
        ((float4*)g_F0)[G] = w0;
        ((float4*)g_F1)[G] = w1;
        ((float4*)g_F2)[G] = w2;

        const int4* tp = (const int4*)tags;
        int4 tg = tp[G];                              // tags[4G..4G+3] = t-1..t+2
        bool r3v = (4 * G + 4 < T_LEN);
        int tg4 = r3v ? __ldg(&tags[4 * G + 4]) : 0;

        int prev = tg.x, cur;
        cur = tg.y; gold += ((cur==0)?w0.x:(cur==1)?w1.x:w2.x) + sTr[cur*5+prev]; prev = cur;
        cur = tg.z; gold += ((cur==0)?w0.y:(cur==1)?w1.y:w2.y) + sTr[cur*5+prev]; prev = cur;
        cur = tg.w; gold += ((cur==0)?w0.z:(cur==1)?w1.z:w2.z) + sTr[cur*5+prev]; prev = cur;
        if (r3v) {
            cur = tg4;  gold += ((cur==0)?w0.w:(cur==1)?w1.w:w2.w) + sTr[cur*5+prev];
        }

        f0s[0]=w0.x; f0s[1]=w0.y; f0s[2]=w0.z; f0s[3]=w0.w;
        f1s[0]=w1.x; f1s[1]=w1.y; f1s[2]=w1.z; f1s[3]=w1.w;
        f2s[0]=w2.x; f2s[1]=w2.y; f2s[2]=w2.z; f2s[3]=w2.w;
        n4 = min(4, T_LEN - (4 * G + 1));
    }

    // per-block gold (ordered tree)
    sRed[tid] = gold;
    __syncthreads();
    for (int k = 128; k > 0; k >>= 1) {
        if (tid < k) sRed[tid] += sRed[tid + k];
        __syncthreads();
    }
    if (tid == 0) g_goldB[blockIdx.x] = sRed[0];

    // 4-step linear-domain matrix
    float P[9] = {1.f,0.f,0.f, 0.f,1.f,0.f, 0.f,0.f,1.f};
    int base = 0;
#pragma unroll
    for (int s = 0; s < 4; ++s) {
        if (s < n4) {
            float e0 = exp2f(L2E * f0s[s]), e1 = exp2f(L2E * f1s[s]), e2 = exp2f(L2E * f2s[s]);
            float a0 = e0*Tl[0], a1 = e0*Tl[1], a2 = e0*Tl[2];
            float b0 = e1*Tl[3], b1 = e1*Tl[4], b2 = e1*Tl[5];
            float d0 = e2*Tl[6], d1 = e2*Tl[7], d2 = e2*Tl[8];
            float q0 = a0*P[0] + a1*P[3] + a2*P[6];
            float q1 = a0*P[1] + a1*P[4] + a2*P[7];
            float q2 = a0*P[2] + a1*P[5] + a2*P[8];
            float q3 = b0*P[0] + b1*P[3] + b2*P[6];
            float q4 = b0*P[1] + b1*P[4] + b2*P[7];
            float q5 = b0*P[2] + b1*P[5] + b2*P[8];
            float q6 = d0*P[0] + d1*P[3] + d2*P[6];
            float q7 = d0*P[1] + d1*P[4] + d2*P[7];
            float q8 = d0*P[2] + d1*P[5] + d2*P[8];
            P[0]=q0;P[1]=q1;P[2]=q2;P[3]=q3;P[4]=q4;P[5]=q5;P[6]=q6;P[7]=q7;P[8]=q8;
        }
    }
    renorm9(P, base);

    // warp Kogge-Stone inclusive scan (later interval on left)
#pragma unroll
    for (int s = 1; s < 32; s <<= 1) {
        float A[9];
#pragma unroll
        for (int i = 0; i < 9; ++i) A[i] = __shfl_up_sync(0xFFFFFFFFu, P[i], s);
        int ab = __shfl_up_sync(0xFFFFFFFFu, base, s);
        if (lane >= s) {
            float C[9];
            mm9(P, A, C);
            base += ab;
            renorm9(C, base);
#pragma unroll
            for (int i = 0; i < 9; ++i) P[i] = C[i];
        }
    }
    if (lane == 31) {
#pragma unroll
        for (int i = 0; i < 9; ++i) sT9[wid][i] = P[i];
        sbT[wid] = base;
    }
    __syncthreads();
    if (tid < 8) {
        float E[9] = {1.f,0.f,0.f, 0.f,1.f,0.f, 0.f,0.f,1.f};
        int be = 0;
        for (int k = 0; k < tid; ++k) {
            float Tk[9], C[9];
#pragma unroll
            for (int i = 0; i < 9; ++i) Tk[i] = sT9[k][i];
            mm9(Tk, E, C);
            be += sbT[k];
            renorm9(C, be);
#pragma unroll
            for (int i = 0; i < 9; ++i) E[i] = C[i];
        }
#pragma unroll
        for (int i = 0; i < 9; ++i) sWE[tid][i] = E[i];
        sbWE[tid] = be;
    }
    __syncthreads();
    {
        float WE[9], C[9];
#pragma unroll
        for (int i = 0; i < 9; ++i) WE[i] = sWE[wid][i];
        mm9(P, WE, C);
        int bb = base + sbWE[wid];
        renorm9(C, bb);
#pragma unroll
        for (int i = 0; i < 9; ++i) g_Pinc[i * PAD0 + G] = C[i];
        g_pb[G] = bb;
        if (tid == 255) {
#pragma unroll
            for (int i = 0; i < 9; ++i) g_Mblk[blockIdx.x][i] = C[i];
            g_Bblk[blockIdx.x] = bb;
        }
    }

    // -------- last-block ticket: exclusive scan over NBLK0 block totals --------
    if (tid == 0) {
        __threadfence();
        unsigned v = atomicAdd(&g_tick1, 1u);
        sLast = (v == (unsigned)(NBLK0 - 1));
    }
    __syncthreads();
    if (!sLast) return;

    {
        float tot[9] = {1.f,0.f,0.f, 0.f,1.f,0.f, 0.f,0.f,1.f};
        int bt = 0;
#pragma unroll
        for (int k = 0; k < K2_ITEMS; ++k) {
            int i = tid * K2_ITEMS + k;
            if (i < NBLK0) {
                float M[9], C[9];
#pragma unroll
                for (int j = 0; j < 9; ++j) M[j] = g_Mblk[i][j];
                mm9(M, tot, C);
                bt += g_Bblk[i];
                renorm9(C, bt);
#pragma unroll
                for (int j = 0; j < 9; ++j) tot[j] = C[j];
            }
        }
#pragma unroll
        for (int j = 0; j < 9; ++j) sP[tid][j] = tot[j];
        sB[tid] = bt;
    }
    __syncthreads();
    for (int s = 1; s < 256; s <<= 1) {
        float A[9], C[9]; int nb = 0; bool act = (tid >= s);
        if (act) {
            float Bm[9];
#pragma unroll
            for (int j = 0; j < 9; ++j) { Bm[j] = sP[tid][j]; A[j] = sP[tid - s][j]; }
            nb = sB[tid] + sB[tid - s];
            mm9(Bm, A, C);
            renorm9(C, nb);
        }
        __syncthreads();
        if (act) {
#pragma unroll
            for (int j = 0; j < 9; ++j) sP[tid][j] = C[j];
            sB[tid] = nb;
        }
        __syncthreads();
    }
    {
        float E[9]; int be;
        if (tid == 0) {
#pragma unroll
            for (int j = 0; j < 9; ++j) E[j] = (j % 4 == 0) ? 1.f : 0.f;
            be = 0;
        } else {
#pragma unroll
            for (int j = 0; j < 9; ++j) E[j] = sP[tid - 1][j];
            be = sB[tid - 1];
        }
#pragma unroll
        for (int k = 0; k < K2_ITEMS; ++k) {
            int i = tid * K2_ITEMS + k;
            if (i < NBLK0) {
#pragma unroll
                for (int j = 0; j < 9; ++j) g_Ebf[i][j] = E[j];
                g_EbB[i] = be;
                float M[9], C[9];
#pragma unroll
                for (int j = 0; j < 9; ++j) M[j] = g_Mblk[i][j];
                mm9(M, E, C);
                be += g_Bblk[i];
                renorm9(C, be);
#pragma unroll
                for (int j = 0; j < 9; ++j) E[j] = C[j];
            }
        }
    }
    if (tid == 0) {
        double v0[3];
        for (int i = 0; i < 3; ++i) {
            double a[5]; double m = -1e300;
            for (int j = 0; j < 5; ++j) {
                a[j] = (double)trans[i * NTAGS + j] + ((j == START_T) ? 0.0 : -10000.0);
                if (a[j] > m) m = a[j];
            }
            double ss = 0.0;
            for (int j = 0; j < 5; ++j) ss += exp(a[j] - m);
            v0[i] = m + log(ss) + (double)feats[i];
        }
        double c0 = fmax(fmax(v0[0], v0[1]), v0[2]);
        g_c0d = c0;
        for (int j = 0; j < 3; ++j) {
            g_u0f[j] = (float)exp(v0[j] - c0);
            g_v0f[j] = (float)v0[j];
        }
        g_tick1 = 0;
    }
}

// ========== K2: boundaries (from odd-G prefixes) + emulation + epilogue ==========
__global__ void __launch_bounds__(256) k_emulate(
        const float* __restrict__ feats, const int* __restrict__ tags,
        const float* __restrict__ trans, float* __restrict__ out) {
    __shared__ float  sTr[25];
    __shared__ double sPart[256];
    __shared__ bool   sLast;
    int tid = threadIdx.x, lane = tid & 31;
    if (tid < 25) sTr[tid] = trans[tid];
    __syncthreads();

    int g = blockIdx.x * 256 + tid;

    float u0[3] = {g_u0f[0], g_u0f[1], g_u0f[2]};
    double c0d = g_c0d;

    // inclusive boundary Bn at step 8g+8: global prefix at G-lane i1 = 2g+1
    int i1 = 2 * g + 1;
    int b1 = i1 >> 8;
    float Eb[9]; int bE = g_EbB[b1];
#pragma unroll
    for (int i = 0; i < 9; ++i) Eb[i] = g_Ebf[b1][i];
    float Pg[9]; int bI = g_pb[i1];
#pragma unroll
    for (int i = 0; i < 9; ++i) Pg[i] = g_Pinc[i * PAD0 + i1];
    float M[9]; int bM = bI + bE;
    mm9(Pg, Eb, M);
    renorm9(M, bM);
    double tB = (double)bM * LN2_D + c0d;
    float Bn0 = (float)((double)__logf(M[0]*u0[0] + M[1]*u0[1] + M[2]*u0[2]) + tB);
    float Bn1 = (float)((double)__logf(M[3]*u0[0] + M[4]*u0[1] + M[5]*u0[2]) + tB);
    float Bn2 = (float)((double)__logf(M[6]*u0[0] + M[7]*u0[1] + M[8]*u0[2]) + tB);

    // start vector A at step 8g = previous lane's Bn
    float A0 = __shfl_up_sync(0xFFFFFFFFu, Bn0, 1);
    float A1 = __shfl_up_sync(0xFFFFFFFFu, Bn1, 1);
    float A2 = __shfl_up_sync(0xFFFFFFFFu, Bn2, 1);
    if (lane == 0) {
        if (g == 0) {
            A0 = g_v0f[0]; A1 = g_v0f[1]; A2 = g_v0f[2];
        } else {
            int i0 = 2 * g - 1;
            int b0 = i0 >> 8;
            float Eb0[9]; int bE0 = g_EbB[b0];
#pragma unroll
            for (int i = 0; i < 9; ++i) Eb0[i] = g_Ebf[b0][i];
            float Pm[9]; int bm = g_pb[i0];
#pragma unroll
            for (int i = 0; i < 9; ++i) Pm[i] = g_Pinc[i * PAD0 + i0];
            float Mm[9]; int b2 = bm + bE0;
            mm9(Pm, Eb0, Mm);
            renorm9(Mm, b2);
            double t2 = (double)b2 * LN2_D + c0d;
            A0 = (float)((double)__logf(Mm[0]*u0[0] + Mm[1]*u0[1] + Mm[2]*u0[2]) + t2);
            A1 = (float)((double)__logf(Mm[3]*u0[0] + Mm[4]*u0[1] + Mm[5]*u0[2]) + t2);
            A2 = (float)((double)__logf(Mm[6]*u0[0] + Mm[7]*u0[1] + Mm[8]*u0[2]) + t2);
        }
    }

    // fp32 absolute-scale quantized walk (bit-path preserved)
    const float4* F04 = (const float4*)g_F0;
    const float4* F14 = (const float4*)g_F1;
    const float4* F24 = (const float4*)g_F2;
    float4 x0a = F04[2*g], x0b = F04[2*g+1];
    float4 x1a = F14[2*g], x1b = F14[2*g+1];
    float4 x2a = F24[2*g], x2b = F24[2*g+1];
    float f0s[8] = {x0a.x,x0a.y,x0a.z,x0a.w, x0b.x,x0b.y,x0b.z,x0b.w};
    float f1s[8] = {x1a.x,x1a.y,x1a.z,x1a.w, x1b.x,x1b.y,x1b.z,x1b.w};
    float f2s[8] = {x2a.x,x2a.y,x2a.z,x2a.w, x2b.x,x2b.y,x2b.z,x2b.w};

    float t00 = sTr[0],  t01 = sTr[1],  t02 = sTr[2];
    float t10 = sTr[5],  t11 = sTr[6],  t12 = sTr[7];
    float t20 = sTr[10], t21 = sTr[11], t22 = sTr[12];

    float fv0 = A0, fv1 = A1, fv2 = A2;
    int n = T_LEN - 1 - g * CHUNK; n = min(n, CHUNK);

#pragma unroll
    for (int s = 0; s < CHUNK; ++s) {
        if (s < n) {
            float f0 = f0s[s], f1 = f1s[s], f2 = f2s[s];
            float a00=__fadd_rn(fv0,t00), a01=__fadd_rn(fv1,t01), a02=__fadd_rn(fv2,t02);
            float a10=__fadd_rn(fv0,t10), a11=__fadd_rn(fv1,t11), a12=__fadd_rn(fv2,t12);
            float a20=__fadd_rn(fv0,t20), a21=__fadd_rn(fv1,t21), a22=__fadd_rn(fv2,t22);
            float m0=fmaxf(fmaxf(a00,a01),a02);
            float m1=fmaxf(fmaxf(a10,a11),a12);
            float m2=fmaxf(fmaxf(a20,a21),a22);
            float s0=__expf(a00-m0)+__expf(a01-m0)+__expf(a02-m0);
            float s1=__expf(a10-m1)+__expf(a11-m1)+__expf(a12-m1);
            float s2=__expf(a20-m2)+__expf(a21-m2)+__expf(a22-m2);
            fv0=__fadd_rn(__fadd_rn(__logf(s0),m0),f0);
            fv1=__fadd_rn(__fadd_rn(__logf(s1),m1),f1);
            fv2=__fadd_rn(__fadd_rn(__logf(s2),m2),f2);
        }
    }

    double part = 0.0;
    if (g < L_LAST) {
        part = (((double)fv0 - (double)Bn0)
              + ((double)fv1 - (double)Bn1)
              + ((double)fv2 - (double)Bn2)) / 3.0;
    } else if (g == L_LAST) {
        g_stop3[0] = __fadd_rn(fv0, sTr[STOP_T * NTAGS + 0]);
        g_stop3[1] = __fadd_rn(fv1, sTr[STOP_T * NTAGS + 1]);
        g_stop3[2] = __fadd_rn(fv2, sTr[STOP_T * NTAGS + 2]);
    }

    sPart[tid] = part;
    __syncthreads();
    for (int k = 128; k > 0; k >>= 1) {
        if (tid < k) sPart[tid] += sPart[tid + k];
        __syncthreads();
    }
    if (tid == 0) g_partB[blockIdx.x] = sPart[0];

    // -------- last-block ticket: final reductions + epilogue --------
    if (tid == 0) {
        __threadfence();
        unsigned v = atomicAdd(&g_tick2, 1u);
        sLast = (v == (unsigned)(NBLK1 - 1));
    }
    __syncthreads();
    if (!sLast) return;

    double s = 0.0;
    for (int i = tid; i < NBLK1; i += 256) s += g_partB[i];
    sPart[tid] = s; __syncthreads();
    for (int k = 128; k > 0; k >>= 1) {
        if (tid < k) sPart[tid] += sPart[tid + k];
        __syncthreads();
    }
    double mu = sPart[0]; __syncthreads();

    double sg = 0.0;
    for (int i = tid; i < NBLK0; i += 256) sg += (double)g_goldB[i];
    sPart[tid] = sg; __syncthreads();
    for (int k = 128; k > 0; k >>= 1) {
        if (tid < k) sPart[tid] += sPart[tid + k];
        __syncthreads();
    }
    double goldsum = sPart[0];

    if (tid == 0) {
        double b0 = (double)g_stop3[0], b1 = (double)g_stop3[1], b2 = (double)g_stop3[2];
        double m = fmax(fmax(b0, b1), b2);
        double alpha = m + log(exp(b0 - m) + exp(b1 - m) + exp(b2 - m)) + mu;

        int tg0 = tags[0];
        int tgL = tags[T_LEN - 1];
        double gold = goldsum
                    + (double)trans[tg0 * NTAGS + START_T]
                    + (double)feats[tg0]
                    + (double)trans[STOP_T * NTAGS + tgL];
        out[0] = (float)(alpha - gold);
        g_tick2 = 0;
    }
}

extern "C" void kernel_launch(void* const* d_in, const int* in_sizes, int n_in,
                              void* d_out, int out_size) {
    const float* feats = nullptr;
    const int*   tags  = nullptr;
    const float* trans = nullptr;
    for (int i = 0; i < n_in; ++i) {
        if (in_sizes[i] == NTAGS * NTAGS)      trans = (const float*)d_in[i];
        else if (in_sizes[i] == T_LEN)         tags  = (const int*)d_in[i];
        else                                   feats = (const float*)d_in[i];
    }
    float* out = (float*)d_out;

    k_stage<<<NBLK0, 256>>>(feats, tags, trans);
    k_emulate<<<NBLK1, 256>>>(feats, tags, trans, out);
}

// round 11
// speedup vs baseline: 2.0141x; 2.0141x over previous
#include <cuda_runtime.h>
#include <math.h>

#define T_LEN   2000000
#define NTAGS   5
#define START_T 3
#define STOP_T  4
#define LN2_D   0.6931471805599453

#define NB      608                   // 4 blocks/SM x 152 SMs — all co-resident
#define CPT     13                    // steps per thread
#define SPB     (256 * CPT)           // 3328 steps per block
#define GPB     (SPB / 4)             // 832 4-row groups per block
#define NGRP    500000
#define SSTR    15                    // smem stride (gcd(15,32)=1 -> conflict-free)
#define GL_LAST 153846                // last active global lane: w0 = 1+13*153846 = 1999999

__device__ float    g_Mblk[NB][9];
__device__ int      g_Bblk[NB];
__device__ float    g_goldB[NB];
__device__ double   g_partB[NB];
__device__ float    g_stop3[3];
__device__ unsigned g_bar, g_tick;

__device__ __forceinline__ void renorm9(float* P, int& base) {
    float m = fmaxf(fmaxf(fmaxf(P[0], P[1]), fmaxf(P[2], P[3])),
                    fmaxf(fmaxf(P[4], P[5]), fmaxf(P[6], fmaxf(P[7], P[8]))));
    int e = (int)(__float_as_uint(m) >> 23) - 127;
    float sc = __uint_as_float((unsigned)(127 - e) << 23);
#pragma unroll
    for (int i = 0; i < 9; ++i) P[i] *= sc;
    base += e;
}

__device__ __forceinline__ void mm9(const float* Bm, const float* A, float* C) {
#pragma unroll
    for (int i = 0; i < 3; ++i)
#pragma unroll
        for (int j = 0; j < 3; ++j)
            C[i*3+j] = Bm[i*3+0]*A[0+j] + Bm[i*3+1]*A[3+j] + Bm[i*3+2]*A[6+j];
}

__global__ void __launch_bounds__(256, 4) crf_fused(
        const float* __restrict__ feats, const int* __restrict__ tags,
        const float* __restrict__ trans, float* __restrict__ out) {
    __shared__ float  sF0[256 * SSTR];
    __shared__ float  sF1[256 * SSTR];
    __shared__ float  sF2[256 * SSTR];
    __shared__ float  sTr[25];
    __shared__ float  sT9[8][9]; __shared__ int sbT[8];
    __shared__ float  sWE[8][9]; __shared__ int sbWE[8];
    __shared__ float  sEb9[9];   __shared__ int sEbB;
    __shared__ double sRD[8];
    __shared__ double sRD2[8];
    __shared__ float  sRF[8];
    __shared__ bool   sLast;

    const float L2E = 1.4426950408889634f;
    int tid = threadIdx.x, lane = tid & 31, wid = tid >> 5, bid = blockIdx.x;
    if (tid < 25) sTr[tid] = trans[tid];
    __syncthreads();

    float Tl[9];
#pragma unroll
    for (int i = 0; i < 3; ++i)
#pragma unroll
        for (int k = 0; k < 3; ++k)
            Tl[i*3+k] = exp2f(L2E * sTr[i * NTAGS + k]);

    // ================= Phase A: coalesced load -> smem + fused gold =================
    float gold = 0.f;
#pragma unroll
    for (int it = 0; it < 4; ++it) {
        int Gl = it * 256 + tid;
        if (Gl < GPB) {
            int G = bid * GPB + Gl;
            if (G < NGRP) {
                const float4* fp = (const float4*)feats;
                int q = 5 * G + 1;
                float4 v0, v1, v2, v3, v4;
                if (G < NGRP - 1) {
                    v0 = fp[q];     v1 = fp[q + 1]; v2 = fp[q + 2];
                    v3 = fp[q + 3]; v4 = fp[q + 4];
                } else {
                    v0 = fp[q];     v1 = fp[q + 1]; v2 = fp[q + 2]; v3 = fp[q + 3];
                    v4 = make_float4(0.f, 0.f, 0.f, 0.f);
                }
                float w0[4] = {v0.y, v1.z, v2.w, v4.x};
                float w1[4] = {v0.z, v1.w, v3.x, v4.y};
                float w2[4] = {v0.w, v2.x, v3.y, v4.z};

                int4 tg = ((const int4*)tags)[G];
                bool r3v = (4 * G + 4 < T_LEN);
                int tg4 = r3v ? __ldg(&tags[4 * G + 4]) : 0;
                int prev = tg.x, cur;
                cur = tg.y; gold += ((cur==0)?w0[0]:(cur==1)?w1[0]:w2[0]) + sTr[cur*5+prev]; prev = cur;
                cur = tg.z; gold += ((cur==0)?w0[1]:(cur==1)?w1[1]:w2[1]) + sTr[cur*5+prev]; prev = cur;
                cur = tg.w; gold += ((cur==0)?w0[2]:(cur==1)?w1[2]:w2[2]) + sTr[cur*5+prev]; prev = cur;
                if (r3v) {
                    cur = tg4; gold += ((cur==0)?w0[3]:(cur==1)?w1[3]:w2[3]) + sTr[cur*5+prev];
                }
#pragma unroll
                for (int r = 0; r < 4; ++r) {
                    int o = 4 * Gl + r;
                    int ln = o / 13, s = o - 13 * ln;
                    int a = ln * SSTR + s;
                    sF0[a] = w0[r]; sF1[a] = w1[r]; sF2[a] = w2[r];
                }
            }
        }
    }
    // gold: warp shfl reduce -> 8 partials -> block total
#pragma unroll
    for (int o = 16; o > 0; o >>= 1) gold += __shfl_down_sync(0xFFFFFFFFu, gold, o);
    if (lane == 0) sRF[wid] = gold;
    __syncthreads();                           // also publishes sF* for matrix phase
    if (tid == 0) {
        float gg = 0.f;
        for (int k = 0; k < 8; ++k) gg += sRF[k];
        g_goldB[bid] = gg;
    }

    // ================= matrices (13 steps, smem features) =================
    int w0t = 1 + bid * SPB + tid * CPT;
    int n = T_LEN - w0t; n = n < 0 ? 0 : (n > CPT ? CPT : n);

    float P[9] = {1.f,0.f,0.f, 0.f,1.f,0.f, 0.f,0.f,1.f};
    int base = 0;
#pragma unroll
    for (int s = 0; s < CPT; ++s) {
        if (s < n) {
            float f0 = sF0[tid*SSTR+s], f1 = sF1[tid*SSTR+s], f2 = sF2[tid*SSTR+s];
            float e0 = exp2f(L2E*f0), e1 = exp2f(L2E*f1), e2 = exp2f(L2E*f2);
            float a0 = e0*Tl[0], a1 = e0*Tl[1], a2 = e0*Tl[2];
            float b0 = e1*Tl[3], b1 = e1*Tl[4], b2 = e1*Tl[5];
            float d0 = e2*Tl[6], d1 = e2*Tl[7], d2 = e2*Tl[8];
            float q0 = a0*P[0] + a1*P[3] + a2*P[6];
            float q1 = a0*P[1] + a1*P[4] + a2*P[7];
            float q2 = a0*P[2] + a1*P[5] + a2*P[8];
            float q3 = b0*P[0] + b1*P[3] + b2*P[6];
            float q4 = b0*P[1] + b1*P[4] + b2*P[7];
            float q5 = b0*P[2] + b1*P[5] + b2*P[8];
            float q6 = d0*P[0] + d1*P[3] + d2*P[6];
            float q7 = d0*P[1] + d1*P[4] + d2*P[7];
            float q8 = d0*P[2] + d1*P[5] + d2*P[8];
            P[0]=q0;P[1]=q1;P[2]=q2;P[3]=q3;P[4]=q4;P[5]=q5;P[6]=q6;P[7]=q7;P[8]=q8;
        }
        if ((s & 3) == 3) renorm9(P, base);
    }
    renorm9(P, base);

    // warp Kogge-Stone inclusive scan (later interval on the left)
#pragma unroll
    for (int s = 1; s < 32; s <<= 1) {
        float A[9];
#pragma unroll
        for (int i = 0; i < 9; ++i) A[i] = __shfl_up_sync(0xFFFFFFFFu, P[i], s);
        int ab = __shfl_up_sync(0xFFFFFFFFu, base, s);
        if (lane >= s) {
            float C[9];
            mm9(P, A, C);
            base += ab;
            renorm9(C, base);
#pragma unroll
            for (int i = 0; i < 9; ++i) P[i] = C[i];
        }
    }
    if (lane == 31) {
#pragma unroll
        for (int i = 0; i < 9; ++i) sT9[wid][i] = P[i];
        sbT[wid] = base;
    }
    __syncthreads();
    if (tid < 8) {
        float E[9] = {1.f,0.f,0.f, 0.f,1.f,0.f, 0.f,0.f,1.f};
        int be = 0;
        for (int k = 0; k < tid; ++k) {
            float Tk[9], C[9];
#pragma unroll
            for (int i = 0; i < 9; ++i) Tk[i] = sT9[k][i];
            mm9(Tk, E, C);
            be += sbT[k];
            renorm9(C, be);
#pragma unroll
            for (int i = 0; i < 9; ++i) E[i] = C[i];
        }
#pragma unroll
        for (int i = 0; i < 9; ++i) sWE[tid][i] = E[i];
        sbWE[tid] = be;
    }
    __syncthreads();

    // thread's block-local inclusive prefix (registers only)
    float Cinc[9]; int bb;
    {
        float WE[9];
#pragma unroll
        for (int i = 0; i < 9; ++i) WE[i] = sWE[wid][i];
        mm9(P, WE, Cinc);
        bb = base + sbWE[wid];
        renorm9(Cinc, bb);
    }
    if (tid == 255) {
#pragma unroll
        for (int i = 0; i < 9; ++i) g_Mblk[bid][i] = Cinc[i];
        g_Bblk[bid] = bb;
    }

    // ================= global barrier (all 608 blocks co-resident) =================
    __syncthreads();
    if (tid == 0) {
        __threadfence();
        atomicAdd(&g_bar, 1u);
        while (*((volatile unsigned*)&g_bar) < (unsigned)NB) __nanosleep(64);
    }
    __syncthreads();
    __threadfence();

    // ================= block-exclusive prefix Eb (warp 0, ordered) =================
    if (wid == 0) {
        float E[9] = {1.f,0.f,0.f, 0.f,1.f,0.f, 0.f,0.f,1.f};
        int be = 0;
        int i0 = lane * 19;
#pragma unroll 1
        for (int k = 0; k < 19; ++k) {
            int i = i0 + k;
            if (i < bid) {
                float M[9], C[9];
#pragma unroll
                for (int j = 0; j < 9; ++j) M[j] = g_Mblk[i][j];
                mm9(M, E, C);
                be += g_Bblk[i];
                renorm9(C, be);
#pragma unroll
                for (int j = 0; j < 9; ++j) E[j] = C[j];
            }
        }
#pragma unroll
        for (int s = 1; s < 32; s <<= 1) {
            float A[9];
#pragma unroll
            for (int j = 0; j < 9; ++j) A[j] = __shfl_up_sync(0xFFFFFFFFu, E[j], s);
            int ab = __shfl_up_sync(0xFFFFFFFFu, be, s);
            if (lane >= s) {
                float C[9];
                mm9(E, A, C);
                be += ab;
                renorm9(C, be);
#pragma unroll
                for (int j = 0; j < 9; ++j) E[j] = C[j];
            }
        }
        if (lane == 31) {
#pragma unroll
            for (int j = 0; j < 9; ++j) sEb9[j] = E[j];
            sEbB = be;
        }
    }
    __syncthreads();

    // ================= boundaries (registers) + emulation walk =================
    // v0 is EXACT in fp32: lse collapses to the START term.
    float v00 = sTr[0*NTAGS+START_T] + __ldg(&feats[0]);
    float v01 = sTr[1*NTAGS+START_T] + __ldg(&feats[1]);
    float v02 = sTr[2*NTAGS+START_T] + __ldg(&feats[2]);
    float c0f = fmaxf(fmaxf(v00, v01), v02);
    double c0d = (double)c0f;
    float u0[3] = {__expf(v00-c0f), __expf(v01-c0f), __expf(v02-c0f)};

    float Eb[9]; int bE = sEbB;
#pragma unroll
    for (int j = 0; j < 9; ++j) Eb[j] = sEb9[j];

    float M9[9]; int bM = bb + bE;
    mm9(Cinc, Eb, M9);
    renorm9(M9, bM);
    double tB = (double)bM * LN2_D + c0d;
    float Bn0 = (float)((double)__logf(M9[0]*u0[0] + M9[1]*u0[1] + M9[2]*u0[2]) + tB);
    float Bn1 = (float)((double)__logf(M9[3]*u0[0] + M9[4]*u0[1] + M9[5]*u0[2]) + tB);
    float Bn2 = (float)((double)__logf(M9[6]*u0[0] + M9[7]*u0[1] + M9[8]*u0[2]) + tB);

    float A0 = __shfl_up_sync(0xFFFFFFFFu, Bn0, 1);
    float A1 = __shfl_up_sync(0xFFFFFFFFu, Bn1, 1);
    float A2 = __shfl_up_sync(0xFFFFFFFFu, Bn2, 1);
    if (lane == 0) {
        if (bid == 0 && tid == 0) {
            A0 = v00; A1 = v01; A2 = v02;
        } else {
            float EX[9]; int bx;
            if (wid == 0) {
#pragma unroll
                for (int j = 0; j < 9; ++j) EX[j] = Eb[j];
                bx = bE;
            } else {
                float W[9];
#pragma unroll
                for (int j = 0; j < 9; ++j) W[j] = sWE[wid][j];
                mm9(W, Eb, EX);
                bx = sbWE[wid] + bE;
                renorm9(EX, bx);
            }
            double tX = (double)bx * LN2_D + c0d;
            A0 = (float)((double)__logf(EX[0]*u0[0] + EX[1]*u0[1] + EX[2]*u0[2]) + tX);
            A1 = (float)((double)__logf(EX[3]*u0[0] + EX[4]*u0[1] + EX[5]*u0[2]) + tX);
            A2 = (float)((double)__logf(EX[6]*u0[0] + EX[7]*u0[1] + EX[8]*u0[2]) + tX);
        }
    }

    double part = 0.0;
    int gl = bid * 256 + tid;
    if (n > 0) {
        float t00 = sTr[0],  t01 = sTr[1],  t02 = sTr[2];
        float t10 = sTr[5],  t11 = sTr[6],  t12 = sTr[7];
        float t20 = sTr[10], t21 = sTr[11], t22 = sTr[12];
        float fv0 = A0, fv1 = A1, fv2 = A2;
#pragma unroll
        for (int s = 0; s < CPT; ++s) {
            if (s < n) {
                float f0 = sF0[tid*SSTR+s], f1 = sF1[tid*SSTR+s], f2 = sF2[tid*SSTR+s];
                float a00=__fadd_rn(fv0,t00), a01=__fadd_rn(fv1,t01), a02=__fadd_rn(fv2,t02);
                float a10=__fadd_rn(fv0,t10), a11=__fadd_rn(fv1,t11), a12=__fadd_rn(fv2,t12);
                float a20=__fadd_rn(fv0,t20), a21=__fadd_rn(fv1,t21), a22=__fadd_rn(fv2,t22);
                float m0=fmaxf(fmaxf(a00,a01),a02);
                float m1=fmaxf(fmaxf(a10,a11),a12);
                float m2=fmaxf(fmaxf(a20,a21),a22);
                float s0=__expf(a00-m0)+__expf(a01-m0)+__expf(a02-m0);
                float s1=__expf(a10-m1)+__expf(a11-m1)+__expf(a12-m1);
                float s2=__expf(a20-m2)+__expf(a21-m2)+__expf(a22-m2);
                fv0=__fadd_rn(__fadd_rn(__logf(s0),m0),f0);
                fv1=__fadd_rn(__fadd_rn(__logf(s1),m1),f1);
                fv2=__fadd_rn(__fadd_rn(__logf(s2),m2),f2);
            }
        }
        if (gl < GL_LAST) {
            part = (((double)fv0 - (double)Bn0)
                  + ((double)fv1 - (double)Bn1)
                  + ((double)fv2 - (double)Bn2)) / 3.0;
        } else if (gl == GL_LAST) {
            g_stop3[0] = __fadd_rn(fv0, sTr[STOP_T * NTAGS + 0]);
            g_stop3[1] = __fadd_rn(fv1, sTr[STOP_T * NTAGS + 1]);
            g_stop3[2] = __fadd_rn(fv2, sTr[STOP_T * NTAGS + 2]);
        }
    }

    // part: warp shfl reduce -> block total
#pragma unroll
    for (int o = 16; o > 0; o >>= 1) part += __shfl_down_sync(0xFFFFFFFFu, part, o);
    if (lane == 0) sRD[wid] = part;
    __syncthreads();
    if (tid == 0) {
        double pp = 0.0;
        for (int k = 0; k < 8; ++k) pp += sRD[k];
        g_partB[bid] = pp;
        __threadfence();
        unsigned v = atomicAdd(&g_tick, 1u);
        sLast = (v == (unsigned)(NB - 1));
    }
    __syncthreads();
    if (!sLast) return;
    __threadfence();

    // ================= final epilogue (last block) =================
    double s = 0.0;
    for (int i = tid; i < NB; i += 256) s += g_partB[i];
#pragma unroll
    for (int o = 16; o > 0; o >>= 1) s += __shfl_down_sync(0xFFFFFFFFu, s, o);
    if (lane == 0) sRD[wid] = s;

    double sg = 0.0;
    for (int i = tid; i < NB; i += 256) sg += (double)g_goldB[i];
#pragma unroll
    for (int o = 16; o > 0; o >>= 1) sg += __shfl_down_sync(0xFFFFFFFFu, sg, o);
    if (lane == 0) sRD2[wid] = sg;
    __syncthreads();

    if (tid == 0) {
        double mu = 0.0, goldsum = 0.0;
        for (int k = 0; k < 8; ++k) { mu += sRD[k]; goldsum += sRD2[k]; }

        double b0 = (double)g_stop3[0], b1 = (double)g_stop3[1], b2 = (double)g_stop3[2];
        double m = fmax(fmax(b0, b1), b2);
        double alpha = m + log(exp(b0 - m) + exp(b1 - m) + exp(b2 - m)) + mu;

        int tg0 = tags[0];
        int tgL = tags[T_LEN - 1];
        double gold = goldsum
                    + (double)trans[tg0 * NTAGS + START_T]
                    + (double)feats[tg0]
                    + (double)trans[STOP_T * NTAGS + tgL];
        out[0] = (float)(alpha - gold);

        g_bar = 0;                    // reset for graph replay
        g_tick = 0;
    }
}

extern "C" void kernel_launch(void* const* d_in, const int* in_sizes, int n_in,
                              void* d_out, int out_size) {
    const float* feats = nullptr;
    const int*   tags  = nullptr;
    const float* trans = nullptr;
    for (int i = 0; i < n_in; ++i) {
        if (in_sizes[i] == NTAGS * NTAGS)      trans = (const float*)d_in[i];
        else if (in_sizes[i] == T_LEN)         tags  = (const int*)d_in[i];
        else                                   feats = (const float*)d_in[i];
    }
    float* out = (float*)d_out;

    crf_fused<<<NB, 256>>>(feats, tags, trans, out);
}